// round 4
// baseline (speedup 1.0000x reference)
#include <cuda_runtime.h>
#include <cstdint>
#include <cstring>

#define BATCH 1024
#define NUM_CLS 58

typedef unsigned long long ull;

// ---------------- device scratch (no allocations allowed) ----------------
__device__ uint4 g_a1[BATCH * 15 * 15];   // packed signs after conv0+pool  [b][py*15+px][4 words]
__device__ unsigned g_pw1[9 * 4 * 128];   // packed w1 signs, layout [tap][word][oc]
__device__ unsigned g_pw2[9 * 4 * 128];
__device__ unsigned g_pw3[9 * 4 * 128];
__device__ unsigned g_pw4[4 * 128];       // layout [word][oc]

// ---------------- f32x2 helpers (packed dual-fp32, sm_103a) ----------------
__device__ __forceinline__ ull pk(float a, float b) {
    ull r;
    asm("mov.b64 %0, {%1, %2};" : "=l"(r) : "f"(a), "f"(b));
    return r;
}
__device__ __forceinline__ void fma2(ull& d, ull a, ull b) {
    asm("fma.rn.f32x2 %0, %1, %2, %0;" : "+l"(d) : "l"(a), "l"(b));
}
__device__ __forceinline__ float2 upk(ull v) {
    float2 f;
    asm("mov.b64 {%0, %1}, %2;" : "=f"(f.x), "=f"(f.y) : "l"(v));
    return f;
}

// ---------------- weight sign packing (warp-ballot, coalesced) ----------------
// 2048 warps: warp -> (tensor t = gw>>9, r = gw&511, oc = r>>2, wi = r&3)
// For 3x3 tensors: lane = input channel within word; each lane reads its 9 taps
// contiguously, 9 ballots produce the 9 packed words.
__global__ void pack_weights_kernel(const float* __restrict__ w1, const float* __restrict__ w2,
                                    const float* __restrict__ w3, const float* __restrict__ w4) {
    int gw   = (blockIdx.x * blockDim.x + threadIdx.x) >> 5;
    int lane = threadIdx.x & 31;
    if (gw >= 2048) return;
    int t  = gw >> 9;
    int r  = gw & 511;
    int oc = r >> 2;
    int wi = r & 3;
    if (t < 3) {
        const float* w = (t == 0) ? w1 : ((t == 1) ? w2 : w3);
        unsigned* pw   = (t == 0) ? g_pw1 : ((t == 1) ? g_pw2 : g_pw3);
        const float* p = w + ((size_t)(oc * 128 + wi * 32 + lane)) * 9;
        float v[9];
#pragma unroll
        for (int k = 0; k < 9; k++) v[k] = p[k];
        unsigned myword = 0;
#pragma unroll
        for (int tap = 0; tap < 9; tap++) {
            unsigned wd = __ballot_sync(0xffffffffu, v[tap] >= 0.0f);
            if (lane == tap) myword = wd;
        }
        if (lane < 9) pw[(lane * 4 + wi) * 128 + oc] = myword;
    } else {
        float v = w4[oc * 128 + wi * 32 + lane];
        unsigned wd = __ballot_sync(0xffffffffu, v >= 0.0f);
        if (lane == 0) g_pw4[wi * 128 + oc] = wd;
    }
}

// ---------------- stage A: fp32 conv0 (3->128, 3x3) + maxpool2x2 + sign + pack ----------------
// block = image, 256 threads = 8 warps. warp -> (channel group cg = warp&3, half = warp>>2)
// Uses packed fma.rn.f32x2: candidate pairs (cx=0,cx=1) share weights; their inputs are
// adjacent row elements, already packed as float2 from shared (lo / mid / hi).
__global__ __launch_bounds__(256) void convA_kernel(const float* __restrict__ x,
                                                    const float* __restrict__ w0) {
    __shared__ float xs[3 * 32 * 32];
    int b = blockIdx.x;
    const float4* xb4 = (const float4*)(x + (size_t)b * 3072);
    float4* xs4 = (float4*)xs;
    for (int i = threadIdx.x; i < 768; i += 256) xs4[i] = xb4[i];
    __syncthreads();

    int warp = threadIdx.x >> 5;
    int lane = threadIdx.x & 31;
    int cg   = warp & 3;
    int half = warp >> 2;
    int oc   = cg * 32 + lane;

    ull wp[27];
#pragma unroll
    for (int k = 0; k < 27; k++) {
        float w = w0[oc * 27 + k];
        wp[k] = pk(w, w);
    }

    unsigned* a1w = (unsigned*)g_a1;

    for (int p = half; p < 225; p += 2) {
        int py = p / 15, px = p - py * 15;
        int y0 = 2 * py, x0 = 2 * px;   // x0 even -> float2 aligned

        ull a01 = 0ull, a23 = 0ull;     // {acc(cy,cx=0), acc(cy,cx=1)} for cy=0 / cy=1
#pragma unroll
        for (int c = 0; c < 3; c++) {
            ull lop[4], mid[4], hip[4];
#pragma unroll
            for (int dy = 0; dy < 4; dy++) {
                const float2* r2 = (const float2*)&xs[c * 1024 + (y0 + dy) * 32 + x0];
                float2 lo = r2[0];
                float2 hi = r2[1];
                lop[dy] = pk(lo.x, lo.y);   // (e0,e1)
                mid[dy] = pk(lo.y, hi.x);   // (e1,e2)
                hip[dy] = pk(hi.x, hi.y);   // (e2,e3)
            }
#pragma unroll
            for (int ky = 0; ky < 3; ky++) {
                fma2(a01, lop[ky],     wp[c * 9 + ky * 3 + 0]);
                fma2(a23, lop[ky + 1], wp[c * 9 + ky * 3 + 0]);
                fma2(a01, mid[ky],     wp[c * 9 + ky * 3 + 1]);
                fma2(a23, mid[ky + 1], wp[c * 9 + ky * 3 + 1]);
                fma2(a01, hip[ky],     wp[c * 9 + ky * 3 + 2]);
                fma2(a23, hip[ky + 1], wp[c * 9 + ky * 3 + 2]);
            }
        }
        float2 v01 = upk(a01);
        float2 v23 = upk(a23);
        float best = fmaxf(fmaxf(v01.x, v01.y), fmaxf(v23.x, v23.y));

        unsigned word = __ballot_sync(0xffffffffu, best >= 0.0f);
        if (lane == 0) a1w[((size_t)b * 225 + p) * 4 + cg] = word;
    }
}

// ---------------- fused stages B+C+D ----------------
// block = image, 256 threads.
// Phase 1: binconv1 (3x3, 15x15->13x13) + pool2x2 -> 6x6 signs in smem
// Phase 2: binconv2 (3x3, 6x6->4x4) + pool k2 s1 -> 3x3 signs in smem   (w3 prefetch overlapped)
// Phase 3: binconv3 (3x3->1x1) + binconv4 (1x1) + relu + fp32 1x1 + softmax
__global__ __launch_bounds__(256) void fusedBCD_kernel(const float* __restrict__ w5,
                                                       float* __restrict__ out) {
    __shared__ uint4 a1s[225];
    __shared__ unsigned wA[4608];     // w1, later w3
    __shared__ unsigned wB[4608];     // w2
    __shared__ unsigned pw4s[512];
    __shared__ uint4 a2v[36];
    __shared__ uint4 a3v[9];
    __shared__ unsigned s4w[4];
    __shared__ float rs[128];
    __shared__ float lg[NUM_CLS];

    int b   = blockIdx.x;
    int tid = threadIdx.x;
    int warp = tid >> 5;
    int lane = tid & 31;

    if (tid < 225) a1s[tid] = g_a1[(size_t)b * 225 + tid];
#pragma unroll
    for (int i = 0; i < 18; i++) {
        wA[tid + 256 * i] = g_pw1[tid + 256 * i];
        wB[tid + 256 * i] = g_pw2[tid + 256 * i];
    }
    pw4s[tid]       = g_pw4[tid];
    pw4s[tid + 256] = g_pw4[tid + 256];
    __syncthreads();

    // ---- phase 1: binconv1. 8 warps: cg = warp>>1, parity = warp&1 ----
    {
        int cg  = warp >> 1;
        int par = warp & 1;
        int oc  = cg * 32 + lane;

        uint4 wr[9];
#pragma unroll
        for (int tap = 0; tap < 9; tap++) {
            wr[tap].x = wA[(tap * 4 + 0) * 128 + oc];
            wr[tap].y = wA[(tap * 4 + 1) * 128 + oc];
            wr[tap].z = wA[(tap * 4 + 2) * 128 + oc];
            wr[tap].w = wA[(tap * 4 + 3) * 128 + oc];
        }

        for (int p = par; p < 36; p += 2) {
            int py = p / 6, px = p - py * 6;
            int y0 = 2 * py, x0 = 2 * px;

            int smin = 1 << 30;
#pragma unroll
            for (int cy = 0; cy < 2; cy++)
#pragma unroll
                for (int cx = 0; cx < 2; cx++) {
                    int s = 0;
#pragma unroll
                    for (int ky = 0; ky < 3; ky++)
#pragma unroll
                        for (int kx = 0; kx < 3; kx++) {
                            uint4 xv = a1s[(y0 + cy + ky) * 15 + (x0 + cx + kx)];
                            uint4 wv = wr[ky * 3 + kx];
                            s += __popc(xv.x ^ wv.x) + __popc(xv.y ^ wv.y) +
                                 __popc(xv.z ^ wv.z) + __popc(xv.w ^ wv.w);
                        }
                    smin = min(smin, s);
                }
            // dot = 1152 - 2*smin ; sign bit = (dot >= 0)
            unsigned word = __ballot_sync(0xffffffffu, smin <= 576);
            if (lane == 0) ((unsigned*)a2v)[p * 4 + cg] = word;
        }
    }
    __syncthreads();

    // ---- phase 2: binconv2 with wB; overlap prefetch of w3 into registers ----
    unsigned t3[18];
#pragma unroll
    for (int i = 0; i < 18; i++) t3[i] = g_pw3[tid + 256 * i];

    {
        int cg   = warp & 3;
        int half = warp >> 2;
        int oc   = cg * 32 + lane;

        uint4 wr[9];
#pragma unroll
        for (int tap = 0; tap < 9; tap++) {
            wr[tap].x = wB[(tap * 4 + 0) * 128 + oc];
            wr[tap].y = wB[(tap * 4 + 1) * 128 + oc];
            wr[tap].z = wB[(tap * 4 + 2) * 128 + oc];
            wr[tap].w = wB[(tap * 4 + 3) * 128 + oc];
        }

        for (int p = half; p < 9; p += 2) {
            int py = p / 3, px = p - py * 3;

            int smin = 1 << 30;
#pragma unroll
            for (int cy = 0; cy < 2; cy++)
#pragma unroll
                for (int cx = 0; cx < 2; cx++) {
                    int s = 0;
#pragma unroll
                    for (int ky = 0; ky < 3; ky++)
#pragma unroll
                        for (int kx = 0; kx < 3; kx++) {
                            uint4 xv = a2v[(py + cy + ky) * 6 + (px + cx + kx)];
                            uint4 wv = wr[ky * 3 + kx];
                            s += __popc(xv.x ^ wv.x) + __popc(xv.y ^ wv.y) +
                                 __popc(xv.z ^ wv.z) + __popc(xv.w ^ wv.w);
                        }
                    smin = min(smin, s);
                }
            unsigned word = __ballot_sync(0xffffffffu, smin <= 576);
            if (lane == 0) ((unsigned*)a3v)[p * 4 + cg] = word;
        }
    }

    // commit w3 prefetch into wA (binconv1 readers are past the earlier sync)
#pragma unroll
    for (int i = 0; i < 18; i++) wA[tid + 256 * i] = t3[i];
    __syncthreads();

    // ---- phase 3: head (threads 0..127 = output channel) ----
    if (tid < 128) {
        int oc = tid;
        // binconv3: full 3x3 receptive field -> one dot per output channel
        int s = 0;
#pragma unroll
        for (int tap = 0; tap < 9; tap++) {
            uint4 xv = a3v[tap];
            s += __popc(xv.x ^ wA[(tap * 4 + 0) * 128 + oc]);
            s += __popc(xv.y ^ wA[(tap * 4 + 1) * 128 + oc]);
            s += __popc(xv.z ^ wA[(tap * 4 + 2) * 128 + oc]);
            s += __popc(xv.w ^ wA[(tap * 4 + 3) * 128 + oc]);
        }
        unsigned word = __ballot_sync(0xffffffffu, s <= 576);  // sign(1152 - 2s)
        if (lane == 0) s4w[warp] = word;
    }
    __syncthreads();

    if (tid < 128) {
        int oc = tid;
        // binconv4 (1x1) + relu
        int t = 0;
#pragma unroll
        for (int wi = 0; wi < 4; wi++) t += __popc(s4w[wi] ^ pw4s[wi * 128 + oc]);
        rs[oc] = fmaxf((float)(128 - 2 * t), 0.0f);
    }
    __syncthreads();

    // fp32 1x1 conv to NUM_CLS logits
    if (tid < NUM_CLS) {
        float acc = 0.0f;
#pragma unroll 8
        for (int o = 0; o < 128; o++) acc += w5[tid * 128 + o] * rs[o];
        lg[tid] = acc;
    }
    __syncthreads();

    // softmax over NUM_CLS
    if (tid < NUM_CLS) {
        float m = -3.4e38f;
        for (int j = 0; j < NUM_CLS; j++) m = fmaxf(m, lg[j]);
        float den = 0.0f;
        for (int j = 0; j < NUM_CLS; j++) den += expf(lg[j] - m);
        out[(size_t)b * NUM_CLS + tid] = expf(lg[tid] - m) / den;
    }
}

// ---------------- launch ----------------
extern "C" void kernel_launch(void* const* d_in, const int* in_sizes, int n_in,
                              void* d_out, int out_size) {
    const float* x  = (const float*)d_in[0];
    const float* w0 = (const float*)d_in[1];
    const float* w1 = (const float*)d_in[2];
    const float* w2 = (const float*)d_in[3];
    const float* w3 = (const float*)d_in[4];
    const float* w4 = (const float*)d_in[5];
    const float* w5 = (const float*)d_in[6];
    float* out = (float*)d_out;

    pack_weights_kernel<<<256, 256>>>(w1, w2, w3, w4);
    convA_kernel<<<BATCH, 256>>>(x, w0);
    fusedBCD_kernel<<<BATCH, 256>>>(w5, out);
}

// round 5
// speedup vs baseline: 1.1932x; 1.1932x over previous
#include <cuda_runtime.h>
#include <cstdint>

#define BATCH 1024
#define NUM_CLS 58

// ---------------- device scratch (no allocations allowed) ----------------
__device__ unsigned g_pw1[9 * 4 * 128];   // packed w1 signs, layout [tap][word][oc]
__device__ unsigned g_pw2[9 * 4 * 128];
__device__ unsigned g_pw3[9 * 4 * 128];
__device__ unsigned g_pw4[4 * 128];       // layout [word][oc]

// ---------------- weight sign packing (warp-ballot, coalesced) ----------------
__global__ void pack_weights_kernel(const float* __restrict__ w1, const float* __restrict__ w2,
                                    const float* __restrict__ w3, const float* __restrict__ w4) {
    int gw   = (blockIdx.x * blockDim.x + threadIdx.x) >> 5;
    int lane = threadIdx.x & 31;
    if (gw >= 2048) return;
    int t  = gw >> 9;
    int r  = gw & 511;
    int oc = r >> 2;
    int wi = r & 3;
    if (t < 3) {
        const float* w = (t == 0) ? w1 : ((t == 1) ? w2 : w3);
        unsigned* pw   = (t == 0) ? g_pw1 : ((t == 1) ? g_pw2 : g_pw3);
        const float* p = w + ((size_t)(oc * 128 + wi * 32 + lane)) * 9;
        float v[9];
#pragma unroll
        for (int k = 0; k < 9; k++) v[k] = p[k];
        unsigned myword = 0;
#pragma unroll
        for (int tap = 0; tap < 9; tap++) {
            unsigned wd = __ballot_sync(0xffffffffu, v[tap] >= 0.0f);
            if (lane == tap) myword = wd;
        }
        if (lane < 9) pw[(lane * 4 + wi) * 128 + oc] = myword;
    } else {
        float v = w4[oc * 128 + wi * 32 + lane];
        unsigned wd = __ballot_sync(0xffffffffu, v >= 0.0f);
        if (lane == 0) g_pw4[wi * 128 + oc] = wd;
    }
}

// ---------------- single merged model kernel: block = image, 256 threads ----------------
// Phase 0: fp32 conv0 (3->128, 3x3) + maxpool2x2 + sign -> packed a1s (15x15x4w) in smem
// Phase 1: binconv1 (3x3) + pool2x2 -> a2v (6x6) in smem
// Phase 2: binconv2 (3x3) + pool k2 s1 -> a3v (3x3) in smem
// Phase 3: binconv3 (3x3->1x1) + binconv4 (1x1) + relu + fp32 1x1 + softmax
// Binary weights are read register-direct from L2-hot globals (no smem staging).
__global__ __launch_bounds__(256) void model_kernel(const float* __restrict__ x,
                                                    const float* __restrict__ w0,
                                                    const float* __restrict__ w5,
                                                    float* __restrict__ out) {
    __shared__ float xs[3 * 32 * 32];
    __shared__ uint4 a1s[225];
    __shared__ uint4 a2v[36];
    __shared__ uint4 a3v[9];
    __shared__ unsigned s4w[4];
    __shared__ float rs[128];
    __shared__ float lg[NUM_CLS];

    int b    = blockIdx.x;
    int tid  = threadIdx.x;
    int warp = tid >> 5;
    int lane = tid & 31;

    // ---- load image ----
    const float4* xb4 = (const float4*)(x + (size_t)b * 3072);
    float4* xs4 = (float4*)xs;
    for (int i = tid; i < 768; i += 256) xs4[i] = xb4[i];
    __syncthreads();

    // ---- phase 0: conv0 + pool + sign + pack (8 warps: cg = warp&3, half = warp>>2) ----
    {
        int cg   = warp & 3;
        int half = warp >> 2;
        int oc   = cg * 32 + lane;

        float wr[27];
#pragma unroll
        for (int k = 0; k < 27; k++) wr[k] = w0[oc * 27 + k];

        for (int p = half; p < 225; p += 2) {
            int py = p / 15, px = p - py * 15;
            int y0 = 2 * py, x0 = 2 * px;   // x0 even -> float2 aligned

            float acc0 = 0.f, acc1 = 0.f, acc2 = 0.f, acc3 = 0.f;
#pragma unroll
            for (int c = 0; c < 3; c++) {
                float e[4][4];
#pragma unroll
                for (int dy = 0; dy < 4; dy++) {
                    const float2* r2 = (const float2*)&xs[c * 1024 + (y0 + dy) * 32 + x0];
                    float2 lo = r2[0];
                    float2 hi = r2[1];
                    e[dy][0] = lo.x; e[dy][1] = lo.y; e[dy][2] = hi.x; e[dy][3] = hi.y;
                }
#pragma unroll
                for (int ky = 0; ky < 3; ky++)
#pragma unroll
                    for (int kx = 0; kx < 3; kx++) {
                        float w = wr[c * 9 + ky * 3 + kx];
                        acc0 += e[0 + ky][0 + kx] * w;
                        acc1 += e[0 + ky][1 + kx] * w;
                        acc2 += e[1 + ky][0 + kx] * w;
                        acc3 += e[1 + ky][1 + kx] * w;
                    }
            }
            float best = fmaxf(fmaxf(acc0, acc1), fmaxf(acc2, acc3));

            unsigned word = __ballot_sync(0xffffffffu, best >= 0.0f);
            if (lane == 0) ((unsigned*)a1s)[p * 4 + cg] = word;
        }
    }
    __syncthreads();

    // ---- phase 1: binconv1 (8 warps: cg = warp>>1, parity = warp&1) ----
    {
        int cg  = warp >> 1;
        int par = warp & 1;
        int oc  = cg * 32 + lane;

        uint4 wr[9];
#pragma unroll
        for (int tap = 0; tap < 9; tap++) {
            wr[tap].x = g_pw1[(tap * 4 + 0) * 128 + oc];
            wr[tap].y = g_pw1[(tap * 4 + 1) * 128 + oc];
            wr[tap].z = g_pw1[(tap * 4 + 2) * 128 + oc];
            wr[tap].w = g_pw1[(tap * 4 + 3) * 128 + oc];
        }

        for (int p = par; p < 36; p += 2) {
            int py = p / 6, px = p - py * 6;
            int y0 = 2 * py, x0 = 2 * px;

            int smin = 1 << 30;
#pragma unroll
            for (int cy = 0; cy < 2; cy++)
#pragma unroll
                for (int cx = 0; cx < 2; cx++) {
                    int s = 0;
#pragma unroll
                    for (int ky = 0; ky < 3; ky++)
#pragma unroll
                        for (int kx = 0; kx < 3; kx++) {
                            uint4 xv = a1s[(y0 + cy + ky) * 15 + (x0 + cx + kx)];
                            uint4 wv = wr[ky * 3 + kx];
                            s += __popc(xv.x ^ wv.x) + __popc(xv.y ^ wv.y) +
                                 __popc(xv.z ^ wv.z) + __popc(xv.w ^ wv.w);
                        }
                    smin = min(smin, s);
                }
            // dot = 1152 - 2*smin ; sign bit = (dot >= 0)
            unsigned word = __ballot_sync(0xffffffffu, smin <= 576);
            if (lane == 0) ((unsigned*)a2v)[p * 4 + cg] = word;
        }
    }
    __syncthreads();

    // ---- phase 2: binconv2 (8 warps: cg = warp&3, half = warp>>2) ----
    {
        int cg   = warp & 3;
        int half = warp >> 2;
        int oc   = cg * 32 + lane;

        uint4 wr[9];
#pragma unroll
        for (int tap = 0; tap < 9; tap++) {
            wr[tap].x = g_pw2[(tap * 4 + 0) * 128 + oc];
            wr[tap].y = g_pw2[(tap * 4 + 1) * 128 + oc];
            wr[tap].z = g_pw2[(tap * 4 + 2) * 128 + oc];
            wr[tap].w = g_pw2[(tap * 4 + 3) * 128 + oc];
        }

        for (int p = half; p < 9; p += 2) {
            int py = p / 3, px = p - py * 3;

            int smin = 1 << 30;
#pragma unroll
            for (int cy = 0; cy < 2; cy++)
#pragma unroll
                for (int cx = 0; cx < 2; cx++) {
                    int s = 0;
#pragma unroll
                    for (int ky = 0; ky < 3; ky++)
#pragma unroll
                        for (int kx = 0; kx < 3; kx++) {
                            uint4 xv = a2v[(py + cy + ky) * 6 + (px + cx + kx)];
                            uint4 wv = wr[ky * 3 + kx];
                            s += __popc(xv.x ^ wv.x) + __popc(xv.y ^ wv.y) +
                                 __popc(xv.z ^ wv.z) + __popc(xv.w ^ wv.w);
                        }
                    smin = min(smin, s);
                }
            unsigned word = __ballot_sync(0xffffffffu, smin <= 576);
            if (lane == 0) ((unsigned*)a3v)[p * 4 + cg] = word;
        }
    }
    __syncthreads();

    // ---- phase 3: head (threads 0..127 = output channel) ----
    if (tid < 128) {
        int oc = tid;
        int s = 0;
#pragma unroll
        for (int tap = 0; tap < 9; tap++) {
            uint4 xv = a3v[tap];
            s += __popc(xv.x ^ g_pw3[(tap * 4 + 0) * 128 + oc]);
            s += __popc(xv.y ^ g_pw3[(tap * 4 + 1) * 128 + oc]);
            s += __popc(xv.z ^ g_pw3[(tap * 4 + 2) * 128 + oc]);
            s += __popc(xv.w ^ g_pw3[(tap * 4 + 3) * 128 + oc]);
        }
        unsigned word = __ballot_sync(0xffffffffu, s <= 576);  // sign(1152 - 2s)
        if (lane == 0) s4w[warp] = word;
    }
    __syncthreads();

    if (tid < 128) {
        int oc = tid;
        int t = 0;
#pragma unroll
        for (int wi = 0; wi < 4; wi++) t += __popc(s4w[wi] ^ g_pw4[wi * 128 + oc]);
        rs[oc] = fmaxf((float)(128 - 2 * t), 0.0f);
    }
    __syncthreads();

    // fp32 1x1 conv to NUM_CLS logits
    if (tid < NUM_CLS) {
        float acc = 0.0f;
#pragma unroll 8
        for (int o = 0; o < 128; o++) acc += w5[tid * 128 + o] * rs[o];
        lg[tid] = acc;
    }
    __syncthreads();

    // softmax over NUM_CLS
    if (tid < NUM_CLS) {
        float m = -3.4e38f;
        for (int j = 0; j < NUM_CLS; j++) m = fmaxf(m, lg[j]);
        float den = 0.0f;
        for (int j = 0; j < NUM_CLS; j++) den += expf(lg[j] - m);
        out[(size_t)b * NUM_CLS + tid] = expf(lg[tid] - m) / den;
    }
}

// ---------------- launch ----------------
extern "C" void kernel_launch(void* const* d_in, const int* in_sizes, int n_in,
                              void* d_out, int out_size) {
    const float* x  = (const float*)d_in[0];
    const float* w0 = (const float*)d_in[1];
    const float* w1 = (const float*)d_in[2];
    const float* w2 = (const float*)d_in[3];
    const float* w3 = (const float*)d_in[4];
    const float* w4 = (const float*)d_in[5];
    const float* w5 = (const float*)d_in[6];
    float* out = (float*)d_out;

    pack_weights_kernel<<<256, 256>>>(w1, w2, w3, w4);
    model_kernel<<<BATCH, 256>>>(x, w0, w5, out);
}

// round 6
// speedup vs baseline: 1.2428x; 1.0416x over previous
#include <cuda_runtime.h>
#include <cstdint>

#define BATCH 1024
#define NUM_CLS 58

// ---------------- device scratch (no allocations allowed) ----------------
__device__ unsigned g_pw1[9 * 4 * 128];   // packed w1 signs, layout [tap][word][oc]
__device__ unsigned g_pw2[9 * 4 * 128];
__device__ unsigned g_pw3[9 * 4 * 128];
__device__ unsigned g_pw4[4 * 128];       // layout [word][oc]

// ---------------- weight sign packing (warp-ballot, coalesced) ----------------
__global__ void pack_weights_kernel(const float* __restrict__ w1, const float* __restrict__ w2,
                                    const float* __restrict__ w3, const float* __restrict__ w4) {
    int gw   = (blockIdx.x * blockDim.x + threadIdx.x) >> 5;
    int lane = threadIdx.x & 31;
    if (gw >= 2048) return;
    int t  = gw >> 9;
    int r  = gw & 511;
    int oc = r >> 2;
    int wi = r & 3;
    if (t < 3) {
        const float* w = (t == 0) ? w1 : ((t == 1) ? w2 : w3);
        unsigned* pw   = (t == 0) ? g_pw1 : ((t == 1) ? g_pw2 : g_pw3);
        const float* p = w + ((size_t)(oc * 128 + wi * 32 + lane)) * 9;
        float v[9];
#pragma unroll
        for (int k = 0; k < 9; k++) v[k] = p[k];
        unsigned myword = 0;
#pragma unroll
        for (int tap = 0; tap < 9; tap++) {
            unsigned wd = __ballot_sync(0xffffffffu, v[tap] >= 0.0f);
            if (lane == tap) myword = wd;
        }
        if (lane < 9) pw[(lane * 4 + wi) * 128 + oc] = myword;
    } else {
        float v = w4[oc * 128 + wi * 32 + lane];
        unsigned wd = __ballot_sync(0xffffffffu, v >= 0.0f);
        if (lane == 0) g_pw4[wi * 128 + oc] = wd;
    }
}

// ---------------- single merged model kernel: block = image, 128 threads (4 warps) ----------------
// 7 blocks/SM resident -> entire 1024-block grid fits in ONE wave (148*7 = 1036).
// Phase 0: fp32 conv0 (3->128, 3x3) + maxpool2x2 + sign -> packed a1s (15x15x4w) in smem
//          (pixel-paired: 2 pooled pixels share the 4x6 input window, float4 loads)
// Phase 1: binconv1 (3x3) + pool2x2 -> a2v (6x6) in smem
// Phase 2: binconv2 (3x3) + pool k2 s1 -> a3v (3x3) in smem
// Phase 3: binconv3 (3x3->1x1) + binconv4 (1x1) + relu + fp32 1x1 + softmax
__global__ __launch_bounds__(128, 7) void model_kernel(const float* __restrict__ x,
                                                       const float* __restrict__ w0,
                                                       const float* __restrict__ w5,
                                                       float* __restrict__ out) {
    __shared__ float xs[3 * 32 * 32];
    __shared__ uint4 a1s[225];
    __shared__ uint4 a2v[36];
    __shared__ uint4 a3v[9];
    __shared__ unsigned s4w[4];
    __shared__ float rs[128];
    __shared__ float lg[NUM_CLS];

    int b    = blockIdx.x;
    int tid  = threadIdx.x;
    int warp = tid >> 5;
    int lane = tid & 31;

    // ---- load image ----
    const float4* xb4 = (const float4*)(x + (size_t)b * 3072);
    float4* xs4 = (float4*)xs;
    for (int i = tid; i < 768; i += 128) xs4[i] = xb4[i];
    __syncthreads();

    // ---- phase 0: conv0 + pool + sign + pack (4 warps: cg = warp) ----
    {
        int cg = warp;
        int oc = cg * 32 + lane;

        float wr[27];
#pragma unroll
        for (int k = 0; k < 27; k++) wr[k] = w0[oc * 27 + k];

        for (int py = 0; py < 15; py++) {
            int y0 = 2 * py;
#pragma unroll
            for (int pxp = 0; pxp < 15; pxp += 2) {
                int x0 = 2 * pxp;            // multiple of 4 -> float4 aligned
                bool pair = (pxp + 1) < 15;

                float a0 = 0.f, a1 = 0.f, a2 = 0.f, a3 = 0.f;   // pixel pxp candidates
                float a4 = 0.f, a5 = 0.f, a6 = 0.f, a7 = 0.f;   // pixel pxp+1 candidates
#pragma unroll
                for (int c = 0; c < 3; c++) {
                    float e[4][6];
#pragma unroll
                    for (int dy = 0; dy < 4; dy++) {
                        const float* row = &xs[c * 1024 + (y0 + dy) * 32 + x0];
                        float4 q = *(const float4*)row;
                        e[dy][0] = q.x; e[dy][1] = q.y; e[dy][2] = q.z; e[dy][3] = q.w;
                        if (pair) {
                            float2 t = *(const float2*)(row + 4);
                            e[dy][4] = t.x; e[dy][5] = t.y;
                        } else {
                            e[dy][4] = 0.f; e[dy][5] = 0.f;
                        }
                    }
#pragma unroll
                    for (int ky = 0; ky < 3; ky++)
#pragma unroll
                        for (int kx = 0; kx < 3; kx++) {
                            float w = wr[c * 9 + ky * 3 + kx];
                            a0 += e[0 + ky][0 + kx] * w;
                            a1 += e[0 + ky][1 + kx] * w;
                            a2 += e[1 + ky][0 + kx] * w;
                            a3 += e[1 + ky][1 + kx] * w;
                            a4 += e[0 + ky][2 + kx] * w;
                            a5 += e[0 + ky][3 + kx] * w;
                            a6 += e[1 + ky][2 + kx] * w;
                            a7 += e[1 + ky][3 + kx] * w;
                        }
                }
                float best0 = fmaxf(fmaxf(a0, a1), fmaxf(a2, a3));
                float best1 = fmaxf(fmaxf(a4, a5), fmaxf(a6, a7));

                int p = py * 15 + pxp;
                unsigned word0 = __ballot_sync(0xffffffffu, best0 >= 0.0f);
                unsigned word1 = __ballot_sync(0xffffffffu, best1 >= 0.0f);
                if (lane == 0) {
                    ((unsigned*)a1s)[p * 4 + cg] = word0;
                    if (pair) ((unsigned*)a1s)[(p + 1) * 4 + cg] = word1;
                }
            }
        }
    }
    __syncthreads();

    // ---- phase 1: binconv1 (4 warps: cg = warp, 36 pixels each) ----
    {
        int cg = warp;
        int oc = cg * 32 + lane;

        uint4 wr[9];
#pragma unroll
        for (int tap = 0; tap < 9; tap++) {
            wr[tap].x = g_pw1[(tap * 4 + 0) * 128 + oc];
            wr[tap].y = g_pw1[(tap * 4 + 1) * 128 + oc];
            wr[tap].z = g_pw1[(tap * 4 + 2) * 128 + oc];
            wr[tap].w = g_pw1[(tap * 4 + 3) * 128 + oc];
        }

        for (int p = 0; p < 36; p++) {
            int py = p / 6, px = p - py * 6;
            int y0 = 2 * py, x0 = 2 * px;

            int smin = 1 << 30;
#pragma unroll
            for (int cy = 0; cy < 2; cy++)
#pragma unroll
                for (int cx = 0; cx < 2; cx++) {
                    int s = 0;
#pragma unroll
                    for (int ky = 0; ky < 3; ky++)
#pragma unroll
                        for (int kx = 0; kx < 3; kx++) {
                            uint4 xv = a1s[(y0 + cy + ky) * 15 + (x0 + cx + kx)];
                            uint4 wv = wr[ky * 3 + kx];
                            s += __popc(xv.x ^ wv.x) + __popc(xv.y ^ wv.y) +
                                 __popc(xv.z ^ wv.z) + __popc(xv.w ^ wv.w);
                        }
                    smin = min(smin, s);
                }
            // dot = 1152 - 2*smin ; sign bit = (dot >= 0)
            unsigned word = __ballot_sync(0xffffffffu, smin <= 576);
            if (lane == 0) ((unsigned*)a2v)[p * 4 + cg] = word;
        }
    }
    __syncthreads();

    // ---- phase 2: binconv2 (4 warps: cg = warp, 9 pixels each) ----
    {
        int cg = warp;
        int oc = cg * 32 + lane;

        uint4 wr[9];
#pragma unroll
        for (int tap = 0; tap < 9; tap++) {
            wr[tap].x = g_pw2[(tap * 4 + 0) * 128 + oc];
            wr[tap].y = g_pw2[(tap * 4 + 1) * 128 + oc];
            wr[tap].z = g_pw2[(tap * 4 + 2) * 128 + oc];
            wr[tap].w = g_pw2[(tap * 4 + 3) * 128 + oc];
        }

        for (int p = 0; p < 9; p++) {
            int py = p / 3, px = p - py * 3;

            int smin = 1 << 30;
#pragma unroll
            for (int cy = 0; cy < 2; cy++)
#pragma unroll
                for (int cx = 0; cx < 2; cx++) {
                    int s = 0;
#pragma unroll
                    for (int ky = 0; ky < 3; ky++)
#pragma unroll
                        for (int kx = 0; kx < 3; kx++) {
                            uint4 xv = a2v[(py + cy + ky) * 6 + (px + cx + kx)];
                            uint4 wv = wr[ky * 3 + kx];
                            s += __popc(xv.x ^ wv.x) + __popc(xv.y ^ wv.y) +
                                 __popc(xv.z ^ wv.z) + __popc(xv.w ^ wv.w);
                        }
                    smin = min(smin, s);
                }
            unsigned word = __ballot_sync(0xffffffffu, smin <= 576);
            if (lane == 0) ((unsigned*)a3v)[p * 4 + cg] = word;
        }
    }
    __syncthreads();

    // ---- phase 3: head (128 threads = output channel) ----
    {
        int oc = tid;
        int s = 0;
#pragma unroll
        for (int tap = 0; tap < 9; tap++) {
            uint4 xv = a3v[tap];
            s += __popc(xv.x ^ g_pw3[(tap * 4 + 0) * 128 + oc]);
            s += __popc(xv.y ^ g_pw3[(tap * 4 + 1) * 128 + oc]);
            s += __popc(xv.z ^ g_pw3[(tap * 4 + 2) * 128 + oc]);
            s += __popc(xv.w ^ g_pw3[(tap * 4 + 3) * 128 + oc]);
        }
        unsigned word = __ballot_sync(0xffffffffu, s <= 576);  // sign(1152 - 2s)
        if (lane == 0) s4w[warp] = word;
    }
    __syncthreads();

    {
        int oc = tid;
        int t = 0;
#pragma unroll
        for (int wi = 0; wi < 4; wi++) t += __popc(s4w[wi] ^ g_pw4[wi * 128 + oc]);
        rs[oc] = fmaxf((float)(128 - 2 * t), 0.0f);
    }
    __syncthreads();

    // fp32 1x1 conv to NUM_CLS logits
    if (tid < NUM_CLS) {
        float acc = 0.0f;
#pragma unroll 8
        for (int o = 0; o < 128; o++) acc += w5[tid * 128 + o] * rs[o];
        lg[tid] = acc;
    }
    __syncthreads();

    // softmax over NUM_CLS
    if (tid < NUM_CLS) {
        float m = -3.4e38f;
        for (int j = 0; j < NUM_CLS; j++) m = fmaxf(m, lg[j]);
        float den = 0.0f;
        for (int j = 0; j < NUM_CLS; j++) den += expf(lg[j] - m);
        out[(size_t)b * NUM_CLS + tid] = expf(lg[tid] - m) / den;
    }
}

// ---------------- launch ----------------
extern "C" void kernel_launch(void* const* d_in, const int* in_sizes, int n_in,
                              void* d_out, int out_size) {
    const float* x  = (const float*)d_in[0];
    const float* w0 = (const float*)d_in[1];
    const float* w1 = (const float*)d_in[2];
    const float* w2 = (const float*)d_in[3];
    const float* w3 = (const float*)d_in[4];
    const float* w4 = (const float*)d_in[5];
    const float* w5 = (const float*)d_in[6];
    float* out = (float*)d_out;

    pack_weights_kernel<<<256, 256>>>(w1, w2, w3, w4);
    model_kernel<<<BATCH, 128>>>(x, w0, w5, out);
}